// round 2
// baseline (speedup 1.0000x reference)
#include <cuda_runtime.h>

// ---------------- problem-size constants ----------------
#define NMAX 50000
#define EMAX 1600000

// ---------------- scratch (device globals: no allocation allowed) --------
__device__ int   g_deg[NMAX];
__device__ float g_dinv[NMAX];
__device__ int   g_rowptr[NMAX + 1];
__device__ int   g_cursor[NMAX];
__device__ int   g_col[EMAX];
__device__ float g_w[EMAX];
__device__ __align__(16) float g_h[(size_t)NMAX * 128];
__device__ __align__(16) float g_a[(size_t)NMAX * 128];
__device__ int g_bsum[64];
__device__ int g_boff[64];
__device__ int g_is64;   // 1 if edge_index is int64, 0 if int32

// ---------------- packed fp32x2 helpers (Blackwell FFMA2) ----------------
__device__ __forceinline__ unsigned long long pack2(float lo, float hi) {
    unsigned long long r;
    asm("mov.b64 %0, {%1, %2};"
        : "=l"(r) : "r"(__float_as_uint(lo)), "r"(__float_as_uint(hi)));
    return r;
}
__device__ __forceinline__ void unpack2(unsigned long long v, float &lo, float &hi) {
    unsigned int a, b;
    asm("mov.b64 {%0, %1}, %2;" : "=r"(a), "=r"(b) : "l"(v));
    lo = __uint_as_float(a);
    hi = __uint_as_float(b);
}
__device__ __forceinline__ void ffma2(unsigned long long &d,
                                      unsigned long long a,
                                      unsigned long long b) {
    asm("fma.rn.f32x2 %0, %1, %2, %0;" : "+l"(d) : "l"(a), "l"(b));
}

// ---------------- edge-index width detection ----------------
__global__ void detect_width_kernel(const unsigned int* __restrict__ p) {
    __shared__ int any;
    if (threadIdx.x == 0) any = 0;
    __syncthreads();
    // Sample first 2048 "elements" interpreted as int64: odd 32-bit words must
    // all be zero if the data really is int64 (indices < 2^31).
    for (int i = threadIdx.x; i < 2048; i += blockDim.x) {
        if (p[2 * i + 1] != 0u) any = 1;
    }
    __syncthreads();
    if (threadIdx.x == 0) g_is64 = any ? 0 : 1;
}

__device__ __forceinline__ void load_edge(const void* ei, int e_total, int idx,
                                          int &src, int &dst) {
    if (g_is64) {
        const long long* p = (const long long*)ei;
        src = (int)p[idx];
        dst = (int)p[e_total + idx];
    } else {
        const int* p = (const int*)ei;
        src = p[idx];
        dst = p[e_total + idx];
    }
}

// ---------------- degree / normalization ----------------
__global__ void zero_deg_kernel(int n) {
    int i = blockIdx.x * blockDim.x + threadIdx.x;
    if (i < n) g_deg[i] = 0;
}

__global__ void count_deg_kernel(const void* __restrict__ ei, int e_total) {
    int idx = blockIdx.x * blockDim.x + threadIdx.x;
    if (idx >= e_total) return;
    int s, d;
    load_edge(ei, e_total, idx, s, d);
    atomicAdd(&g_deg[d], 1);
}

__global__ void dinv_kernel(int n) {
    int i = blockIdx.x * blockDim.x + threadIdx.x;
    if (i < n) g_dinv[i] = rsqrtf((float)(g_deg[i] + 1));  // +1 self loop
}

// ---------------- 3-kernel exclusive scan of g_deg -> g_rowptr -----------
__global__ void scan_part_kernel(int n) {
    __shared__ int sm[1024];
    int i = blockIdx.x * 1024 + threadIdx.x;
    sm[threadIdx.x] = (i < n) ? g_deg[i] : 0;
    __syncthreads();
    for (int s = 512; s > 0; s >>= 1) {
        if (threadIdx.x < s) sm[threadIdx.x] += sm[threadIdx.x + s];
        __syncthreads();
    }
    if (threadIdx.x == 0) g_bsum[blockIdx.x] = sm[0];
}

__global__ void scan_top_kernel(int nblocks) {
    if (threadIdx.x == 0 && blockIdx.x == 0) {
        int run = 0;
        for (int b = 0; b < nblocks; b++) {
            g_boff[b] = run;
            run += g_bsum[b];
        }
    }
}

__global__ void scan_final_kernel(int n) {
    __shared__ int sm[1024];
    int tid = threadIdx.x;
    int i = blockIdx.x * 1024 + tid;
    int v = (i < n) ? g_deg[i] : 0;
    sm[tid] = v;
    __syncthreads();
    for (int off = 1; off < 1024; off <<= 1) {
        int t = (tid >= off) ? sm[tid - off] : 0;
        __syncthreads();
        sm[tid] += t;
        __syncthreads();
    }
    if (i < n) {
        int start = g_boff[blockIdx.x] + sm[tid] - v;   // exclusive
        g_rowptr[i] = start;
        g_cursor[i] = start;
        if (i == n - 1) g_rowptr[n] = start + v;
    }
}

// ---------------- CSC build (dst-sorted edges) ----------------
__global__ void build_csr_kernel(const void* __restrict__ ei, int e_total) {
    int idx = blockIdx.x * blockDim.x + threadIdx.x;
    if (idx >= e_total) return;
    int s, d;
    load_edge(ei, e_total, idx, s, d);
    int pos = atomicAdd(&g_cursor[d], 1);
    g_col[pos] = s;
    g_w[pos]   = g_dinv[s] * g_dinv[d];
}

// ---------------- GEMM: C[M,128] = A[M,128] @ W[128,128], packed f32x2 ----
// Block: 64 rows x 128 cols, 256 threads, each thread 4 rows x 4 col-pairs.
__global__ void __launch_bounds__(256) gemm128_kernel(
    const float* __restrict__ A, const float* __restrict__ W,
    float* __restrict__ C, int M)
{
    __shared__ unsigned long long xs[64][33];   // packed (v, v), padded
    __shared__ unsigned long long ws[32][64];   // packed (W[k][2cp], W[k][2cp+1])

    int tid  = threadIdx.x;
    int row0 = blockIdx.x * 64;
    int cpg  = tid & 15;        // col-pair group: cp = 16*j + cpg
    int rg   = tid >> 4;        // row group: rows rg*4 + i

    unsigned long long acc[4][4];
#pragma unroll
    for (int i = 0; i < 4; i++)
#pragma unroll
        for (int j = 0; j < 4; j++) acc[i][j] = 0ull;

    for (int kb = 0; kb < 128; kb += 32) {
        // load X tile (64 x 32), packed broadcast
        {
            int lr = tid >> 5;
            int lk = tid & 31;
#pragma unroll
            for (int p = 0; p < 8; p++) {
                int r = lr + p * 8;
                int grow = row0 + r;
                float v = (grow < M) ? A[(size_t)grow * 128 + kb + lk] : 0.f;
                xs[r][lk] = pack2(v, v);
            }
        }
        // load W tile (32 x 128), packed col-pairs
        {
#pragma unroll
            for (int p = 0; p < 8; p++) {
                int idx = p * 256 + tid;
                int kk = idx >> 6;
                int cp = idx & 63;
                float2 wv = *reinterpret_cast<const float2*>(&W[(kb + kk) * 128 + cp * 2]);
                ws[kk][cp] = pack2(wv.x, wv.y);
            }
        }
        __syncthreads();

#pragma unroll
        for (int kk = 0; kk < 32; kk++) {
            unsigned long long wv[4], xv[4];
#pragma unroll
            for (int j = 0; j < 4; j++) wv[j] = ws[kk][16 * j + cpg];
#pragma unroll
            for (int i = 0; i < 4; i++) xv[i] = xs[rg * 4 + i][kk];
#pragma unroll
            for (int i = 0; i < 4; i++)
#pragma unroll
                for (int j = 0; j < 4; j++) ffma2(acc[i][j], xv[i], wv[j]);
        }
        __syncthreads();
    }

#pragma unroll
    for (int i = 0; i < 4; i++) {
        int grow = row0 + rg * 4 + i;
        if (grow < M) {
#pragma unroll
            for (int j = 0; j < 4; j++) {
                int cp = 16 * j + cpg;
                float lo, hi;
                unpack2(acc[i][j], lo, hi);
                *reinterpret_cast<float2*>(&C[(size_t)grow * 128 + cp * 2]) =
                    make_float2(lo, hi);
            }
        }
    }
}

// ---------------- aggregation: out = relu(bias + dinv^2*h[i] + sum w*h[src])
// One warp per node; lane handles 4 cols via float4.
__global__ void __launch_bounds__(256) aggregate_kernel(
    const float4* __restrict__ h4, const float* __restrict__ bias,
    float4* __restrict__ out4, int n)
{
    int warp = (blockIdx.x * blockDim.x + threadIdx.x) >> 5;
    int lane = threadIdx.x & 31;
    if (warp >= n) return;
    int node = warp;

    float ds = g_dinv[node];
    float sw = ds * ds;                       // 1/deg (self-loop norm)
    float4 hv = h4[(size_t)node * 32 + lane];
    float4 acc;
    acc.x = sw * hv.x; acc.y = sw * hv.y; acc.z = sw * hv.z; acc.w = sw * hv.w;

    int e   = g_rowptr[node];
    int end = g_rowptr[node + 1];

    // full 32-edge chunks, fully unrolled for MLP
    for (; e + 32 <= end; e += 32) {
        int   src = g_col[e + lane];
        float wv  = g_w[e + lane];
#pragma unroll
        for (int j = 0; j < 32; j++) {
            int   s  = __shfl_sync(0xffffffffu, src, j);
            float ww = __shfl_sync(0xffffffffu, wv, j);
            float4 hj = h4[(size_t)s * 32 + lane];
            acc.x += ww * hj.x; acc.y += ww * hj.y;
            acc.z += ww * hj.z; acc.w += ww * hj.w;
        }
    }
    // tail
    if (e < end) {
        int rem = end - e;
        int   src = (lane < rem) ? g_col[e + lane] : 0;
        float wv  = (lane < rem) ? g_w[e + lane]   : 0.f;
#pragma unroll 4
        for (int j = 0; j < rem; j++) {
            int   s  = __shfl_sync(0xffffffffu, src, j);
            float ww = __shfl_sync(0xffffffffu, wv, j);
            float4 hj = h4[(size_t)s * 32 + lane];
            acc.x += ww * hj.x; acc.y += ww * hj.y;
            acc.z += ww * hj.z; acc.w += ww * hj.w;
        }
    }

    float4 b = ((const float4*)bias)[lane];
    float4 o;
    o.x = fmaxf(acc.x + b.x, 0.f);
    o.y = fmaxf(acc.y + b.y, 0.f);
    o.z = fmaxf(acc.z + b.z, 0.f);
    o.w = fmaxf(acc.w + b.w, 0.f);
    out4[(size_t)node * 32 + lane] = o;
}

// ---------------- classifier: out[M,16] = h[M,128] @ Wc[128,16] + bc ------
__global__ void __launch_bounds__(256) classifier_kernel(
    const float* __restrict__ h, const float* __restrict__ Wc,
    const float* __restrict__ bc, float* __restrict__ out, int n)
{
    __shared__ float ws[128 * 16];
    __shared__ float hs[16][129];
    int tid = threadIdx.x;
    int row0 = blockIdx.x * 16;
#pragma unroll
    for (int p = 0; p < 8; p++) ws[p * 256 + tid] = Wc[p * 256 + tid];
#pragma unroll
    for (int p = 0; p < 8; p++) {
        int idx = p * 256 + tid;
        int r = idx >> 7, c = idx & 127;
        hs[r][c] = (row0 + r < n) ? h[(size_t)(row0 + r) * 128 + c] : 0.f;
    }
    __syncthreads();
    int r = tid >> 4, c = tid & 15;
    float acc = bc[c];
#pragma unroll 16
    for (int k = 0; k < 128; k++) acc = fmaf(hs[r][k], ws[k * 16 + c], acc);
    if (row0 + r < n) out[(size_t)(row0 + r) * 16 + c] = acc;
}

// ---------------- launch ----------------
extern "C" void kernel_launch(void* const* d_in, const int* in_sizes, int n_in,
                              void* d_out, int out_size)
{
    const float* x  = (const float*)d_in[0];
    const void*  ei = d_in[1];
    const float* W1 = (const float*)d_in[2];
    const float* b1 = (const float*)d_in[3];
    const float* W2 = (const float*)d_in[4];
    const float* b2 = (const float*)d_in[5];
    const float* Wc = (const float*)d_in[6];
    const float* bc = (const float*)d_in[7];
    float* out = (float*)d_out;

    int n = in_sizes[0] / 128;
    int e = in_sizes[1] / 2;

    float *h, *a;
    cudaGetSymbolAddress((void**)&h, g_h);
    cudaGetSymbolAddress((void**)&a, g_a);

    int nb1024 = (n + 1023) / 1024;
    int ebk    = (e + 255) / 256;

    detect_width_kernel<<<1, 256>>>((const unsigned int*)ei);
    zero_deg_kernel<<<nb1024, 1024>>>(n);
    count_deg_kernel<<<ebk, 256>>>(ei, e);
    dinv_kernel<<<nb1024, 1024>>>(n);
    scan_part_kernel<<<nb1024, 1024>>>(n);
    scan_top_kernel<<<1, 32>>>(nb1024);
    scan_final_kernel<<<nb1024, 1024>>>(n);
    build_csr_kernel<<<ebk, 256>>>(ei, e);

    // layer 1
    gemm128_kernel<<<(n + 63) / 64, 256>>>(x, W1, h, n);
    aggregate_kernel<<<(n + 7) / 8, 256>>>((const float4*)h, b1, (float4*)a, n);
    // layer 2
    gemm128_kernel<<<(n + 63) / 64, 256>>>(a, W2, h, n);
    aggregate_kernel<<<(n + 7) / 8, 256>>>((const float4*)h, b2, (float4*)a, n);
    // classifier
    classifier_kernel<<<(n + 15) / 16, 256>>>(a, Wc, bc, out, n);
}